// round 1
// baseline (speedup 1.0000x reference)
#include <cuda_runtime.h>
#include <math.h>

#define N_NODES 100000
#define N_EDGES 819200
#define D 512
#define L_LAYERS 3
#define LN_EPS 1e-5f

// ---------------- scratch (static device globals; no allocation) ------------
__device__ float g_agg[(size_t)N_NODES * D];   // ~205 MB
__device__ float g_h  [(size_t)N_NODES * D];   // ~205 MB
__device__ float g_x0 [(size_t)N_NODES * D];   // ~205 MB
__device__ float g_x1 [(size_t)N_NODES * D];   // ~205 MB
__device__ float g_cnt[N_NODES];
__device__ float g_inv[N_NODES];

// ---------------- utility: zero a float buffer (float4 grid-stride) --------
__global__ void zero_kernel(float4* __restrict__ p, size_t n4) {
    size_t i = (size_t)blockIdx.x * blockDim.x + threadIdx.x;
    size_t stride = (size_t)gridDim.x * blockDim.x;
    float4 z = make_float4(0.f, 0.f, 0.f, 0.f);
    for (; i < n4; i += stride) p[i] = z;
}

// ---------------- in-degree counts + inverse --------------------------------
__global__ void count_kernel(const int* __restrict__ ei, float* __restrict__ cnt) {
    int e = blockIdx.x * blockDim.x + threadIdx.x;
    if (e < N_EDGES) {
        int tgt = ei[N_EDGES + e];
        atomicAdd(&cnt[tgt], 1.0f);
    }
}

__global__ void inv_kernel(const float* __restrict__ cnt, float* __restrict__ inv) {
    int i = blockIdx.x * blockDim.x + threadIdx.x;
    if (i < N_NODES) inv[i] = 1.0f / fmaxf(cnt[i], 1.0f);
}

// ---------------- scatter-add: agg[tgt] += x[src] ---------------------------
// one block (128 threads) per edge; each thread moves one float4 (512 floats/edge)
__global__ void __launch_bounds__(128) scatter_kernel(
    const float* __restrict__ x, const int* __restrict__ ei, float* __restrict__ agg)
{
    int e = blockIdx.x;
    int src = ei[e];
    int tgt = ei[N_EDGES + e];
    const float4* xs = (const float4*)(x + (size_t)src * D);
    float4 v = xs[threadIdx.x];
    float* a = agg + (size_t)tgt * D + (size_t)threadIdx.x * 4;
    atomicAdd(a + 0, v.x);
    atomicAdd(a + 1, v.y);
    atomicAdd(a + 2, v.z);
    atomicAdd(a + 3, v.w);
}

// ---------------- GEMM: H = (agg*inv) @ Wl^T + X @ Wr^T + bias --------------
// Classic 128x128x8 SGEMM, 256 threads, 8x8 microtile. Two accumulation
// phases over K=512 each (phase 0: A=agg scaled by inv[row], W=Wl;
// phase 1: A=x, W=Wr).
#define BM 128
#define BN 128
#define BK 8
#define TM 8
#define TN 8

__global__ void __launch_bounds__(256) gemm_kernel(
    const float* __restrict__ A1, const float* __restrict__ inv,
    const float* __restrict__ A2,
    const float* __restrict__ Wl, const float* __restrict__ Wr,
    const float* __restrict__ bias, float* __restrict__ H)
{
    __shared__ float As[BK][BM + 4];
    __shared__ float Bs[BK][BN];

    int tid = threadIdx.x;
    int m0 = blockIdx.x * BM;
    int o0 = blockIdx.y * BN;

    int l_row  = tid >> 1;        // 0..127
    int l_col4 = (tid & 1) * 4;   // 0 or 4

    int ty = tid >> 4;            // 0..15
    int tx = tid & 15;            // 0..15

    int arow = m0 + l_row;        // node row this thread loads for A
    int brow = o0 + l_row;        // weight output-row this thread loads for B

    float acc[TM][TN];
#pragma unroll
    for (int i = 0; i < TM; i++)
#pragma unroll
        for (int j = 0; j < TN; j++) acc[i][j] = 0.f;

#pragma unroll 1
    for (int phase = 0; phase < 2; phase++) {
        const float* A = phase ? A2 : A1;
        const float* W = phase ? Wr : Wl;
        float s = 1.0f;
        if (phase == 0) s = (arow < N_NODES) ? inv[arow] : 0.0f;

#pragma unroll 1
        for (int k0 = 0; k0 < D; k0 += BK) {
            float4 av = make_float4(0.f, 0.f, 0.f, 0.f);
            if (arow < N_NODES)
                av = *(const float4*)(A + (size_t)arow * D + k0 + l_col4);
            float4 bv = *(const float4*)(W + (size_t)brow * D + k0 + l_col4);

            As[l_col4 + 0][l_row] = av.x * s;
            As[l_col4 + 1][l_row] = av.y * s;
            As[l_col4 + 2][l_row] = av.z * s;
            As[l_col4 + 3][l_row] = av.w * s;
            Bs[l_col4 + 0][l_row] = bv.x;
            Bs[l_col4 + 1][l_row] = bv.y;
            Bs[l_col4 + 2][l_row] = bv.z;
            Bs[l_col4 + 3][l_row] = bv.w;
            __syncthreads();

#pragma unroll
            for (int k = 0; k < BK; k++) {
                float a[TM], bb[TN];
#pragma unroll
                for (int i = 0; i < TM; i++) a[i] = As[k][ty * TM + i];
#pragma unroll
                for (int j = 0; j < TN; j++) bb[j] = Bs[k][tx * TN + j];
#pragma unroll
                for (int i = 0; i < TM; i++)
#pragma unroll
                    for (int j = 0; j < TN; j++) acc[i][j] += a[i] * bb[j];
            }
            __syncthreads();
        }
    }

    // epilogue: + bias, store
#pragma unroll
    for (int i = 0; i < TM; i++) {
        int m = m0 + ty * TM + i;
        if (m < N_NODES) {
            float* hrow = H + (size_t)m * D + o0 + tx * TN;
            const float* brow_p = bias + o0 + tx * TN;
#pragma unroll
            for (int j = 0; j < TN; j++) hrow[j] = acc[i][j] + brow_p[j];
        }
    }
}

// ---------------- LayerNorm + ReLU + residual -------------------------------
// one block (128 threads) per row; each thread owns one float4
__global__ void __launch_bounds__(128) ln_kernel(
    const float* __restrict__ H, const float* __restrict__ Xin,
    const float* __restrict__ gg, const float* __restrict__ bb,
    float* __restrict__ Xout)
{
    int row = blockIdx.x;
    int t = threadIdx.x;
    int lane = t & 31, wid = t >> 5;

    float4 v = ((const float4*)(H + (size_t)row * D))[t];
    float s  = v.x + v.y + v.z + v.w;
    float sq = v.x * v.x + v.y * v.y + v.z * v.z + v.w * v.w;

#pragma unroll
    for (int off = 16; off > 0; off >>= 1) {
        s  += __shfl_xor_sync(0xFFFFFFFFu, s,  off);
        sq += __shfl_xor_sync(0xFFFFFFFFu, sq, off);
    }
    __shared__ float ss[4], sqs[4];
    if (lane == 0) { ss[wid] = s; sqs[wid] = sq; }
    __syncthreads();
    s  = ss[0]  + ss[1]  + ss[2]  + ss[3];
    sq = sqs[0] + sqs[1] + sqs[2] + sqs[3];

    float mean = s * (1.0f / D);
    float var  = sq * (1.0f / D) - mean * mean;
    float r    = rsqrtf(var + LN_EPS);

    float4 g4 = ((const float4*)gg)[t];
    float4 b4 = ((const float4*)bb)[t];
    float4 xi = ((const float4*)(Xin + (size_t)row * D))[t];

    float4 o;
    o.x = fmaxf((v.x - mean) * r * g4.x + b4.x, 0.f) + xi.x;
    o.y = fmaxf((v.y - mean) * r * g4.y + b4.y, 0.f) + xi.y;
    o.z = fmaxf((v.z - mean) * r * g4.z + b4.z, 0.f) + xi.z;
    o.w = fmaxf((v.w - mean) * r * g4.w + b4.w, 0.f) + xi.w;
    ((float4*)(Xout + (size_t)row * D))[t] = o;
}

// ---------------- launch ----------------------------------------------------
extern "C" void kernel_launch(void* const* d_in, const int* in_sizes, int n_in,
                              void* d_out, int out_size)
{
    const float* x   = (const float*)d_in[0];
    const int*   ei  = (const int*)  d_in[1];
    const float* Wl  = (const float*)d_in[2];
    const float* Wr  = (const float*)d_in[3];
    const float* b   = (const float*)d_in[4];
    const float* lng = (const float*)d_in[5];
    const float* lnb = (const float*)d_in[6];
    float* out = (float*)d_out;

    float *agg, *h, *x0, *x1, *cnt, *inv;
    cudaGetSymbolAddress((void**)&agg, g_agg);
    cudaGetSymbolAddress((void**)&h,   g_h);
    cudaGetSymbolAddress((void**)&x0,  g_x0);
    cudaGetSymbolAddress((void**)&x1,  g_x1);
    cudaGetSymbolAddress((void**)&cnt, g_cnt);
    cudaGetSymbolAddress((void**)&inv, g_inv);

    const size_t nd = (size_t)N_NODES * D;

    // in-degree counts (recomputed every call: deterministic, cheap)
    zero_kernel<<<(N_NODES / 4 + 255) / 256, 256>>>((float4*)cnt, N_NODES / 4);
    count_kernel<<<(N_EDGES + 255) / 256, 256>>>(ei, cnt);
    inv_kernel<<<(N_NODES + 255) / 256, 256>>>(cnt, inv);

    const float* xin = x;
    float* outs[L_LAYERS] = { x0, x1, out };

    dim3 ggrid((N_NODES + BM - 1) / BM, D / BN);   // (782, 4)

    for (int l = 0; l < L_LAYERS; l++) {
        zero_kernel<<<4096, 256>>>((float4*)agg, nd / 4);
        scatter_kernel<<<N_EDGES, 128>>>(xin, ei, agg);
        gemm_kernel<<<ggrid, 256>>>(agg, inv, xin,
                                    Wl + (size_t)l * D * D,
                                    Wr + (size_t)l * D * D,
                                    b + (size_t)l * D, h);
        ln_kernel<<<N_NODES, 128>>>(h, xin, lng + (size_t)l * D,
                                    lnb + (size_t)l * D, outs[l]);
        xin = outs[l];
    }
}

// round 3
// speedup vs baseline: 1.6909x; 1.6909x over previous
#include <cuda_runtime.h>
#include <cuda_bf16.h>
#include <cstdint>
#include <math.h>

#define N_NODES 100000
#define N_EDGES 819200
#define D 512
#define L_LAYERS 3
#define LN_EPS 1e-5f

// ---------------- scratch (static device globals; no allocation) ------------
__device__ float g_agg[(size_t)N_NODES * D];
__device__ float g_h  [(size_t)N_NODES * D];
__device__ float g_x0 [(size_t)N_NODES * D];
__device__ float g_x1 [(size_t)N_NODES * D];
__device__ float g_cnt[N_NODES];
__device__ float g_inv[N_NODES];
__device__ __align__(16) __nv_bfloat16 g_aH[(size_t)N_NODES * D];
__device__ __align__(16) __nv_bfloat16 g_aL[(size_t)N_NODES * D];
__device__ __align__(16) __nv_bfloat16 g_xH[(size_t)N_NODES * D];
__device__ __align__(16) __nv_bfloat16 g_xL[(size_t)N_NODES * D];
__device__ __align__(16) __nv_bfloat16 g_wlH[D * D];
__device__ __align__(16) __nv_bfloat16 g_wlL[D * D];
__device__ __align__(16) __nv_bfloat16 g_wrH[D * D];
__device__ __align__(16) __nv_bfloat16 g_wrL[D * D];

// ---------------- helpers ---------------------------------------------------
__device__ __forceinline__ uint32_t smem_u32(const void* p) {
    uint32_t a;
    asm("{ .reg .u64 t; cvta.to.shared.u64 t, %1; cvt.u32.u64 %0, t; }"
        : "=r"(a) : "l"(p));
    return a;
}
__device__ __forceinline__ uint32_t pk(__nv_bfloat16 a, __nv_bfloat16 b) {
    uint16_t ua = *(uint16_t*)&a, ub = *(uint16_t*)&b;
    return (uint32_t)ua | ((uint32_t)ub << 16);
}
__device__ __forceinline__ void ldsm4(uint32_t* r, uint32_t addr) {
    asm volatile("ldmatrix.sync.aligned.m8n8.x4.shared.b16 {%0,%1,%2,%3}, [%4];"
                 : "=r"(r[0]), "=r"(r[1]), "=r"(r[2]), "=r"(r[3]) : "r"(addr));
}
__device__ __forceinline__ void mma16816(float* c, const uint32_t* a, const uint32_t* b) {
    asm volatile("mma.sync.aligned.m16n8k16.row.col.f32.bf16.bf16.f32 "
                 "{%0,%1,%2,%3}, {%4,%5,%6,%7}, {%8,%9}, {%0,%1,%2,%3};"
                 : "+f"(c[0]), "+f"(c[1]), "+f"(c[2]), "+f"(c[3])
                 : "r"(a[0]), "r"(a[1]), "r"(a[2]), "r"(a[3]), "r"(b[0]), "r"(b[1]));
}
__device__ __forceinline__ void cp16(uint32_t dst, const void* src, uint32_t bytes) {
    asm volatile("cp.async.cg.shared.global [%0], [%1], 16, %2;"
                 :: "r"(dst), "l"(src), "r"(bytes) : "memory");
}
#define CP_COMMIT() asm volatile("cp.async.commit_group;" ::: "memory")
#define CP_WAIT2()  asm volatile("cp.async.wait_group 2;" ::: "memory")

// ---------------- utility kernels -------------------------------------------
__global__ void zero_kernel(float4* __restrict__ p, size_t n4) {
    size_t i = (size_t)blockIdx.x * blockDim.x + threadIdx.x;
    size_t stride = (size_t)gridDim.x * blockDim.x;
    float4 z = make_float4(0.f, 0.f, 0.f, 0.f);
    for (; i < n4; i += stride) p[i] = z;
}
__global__ void count_kernel(const int* __restrict__ ei, float* __restrict__ cnt) {
    int e = blockIdx.x * blockDim.x + threadIdx.x;
    if (e < N_EDGES) atomicAdd(&cnt[ei[N_EDGES + e]], 1.0f);
}
__global__ void inv_kernel(const float* __restrict__ cnt, float* __restrict__ inv) {
    int i = blockIdx.x * blockDim.x + threadIdx.x;
    if (i < N_NODES) inv[i] = 1.0f / fmaxf(cnt[i], 1.0f);
}

// ---------------- scatter-add: agg[tgt] += x[src] ---------------------------
__global__ void __launch_bounds__(128) scatter_kernel(
    const float* __restrict__ x, const int* __restrict__ ei, float* __restrict__ agg)
{
    int e = blockIdx.x;
    int src = ei[e];
    int tgt = ei[N_EDGES + e];
    const float4* xs = (const float4*)(x + (size_t)src * D);
    float4 v = xs[threadIdx.x];
    float* a = agg + (size_t)tgt * D + (size_t)threadIdx.x * 4;
    atomicAdd(a + 0, v.x);
    atomicAdd(a + 1, v.y);
    atomicAdd(a + 2, v.z);
    atomicAdd(a + 3, v.w);
}

// ---------------- fp32 -> (bf16 hi, bf16 lo) split, optional row scale ------
// one block per row (128 threads x float4); works for any row count via grid
__global__ void __launch_bounds__(128) split_kernel(
    const float* __restrict__ in, const float* __restrict__ rowscale,
    __nv_bfloat16* __restrict__ hi, __nv_bfloat16* __restrict__ lo)
{
    size_t row = blockIdx.x;
    int t = threadIdx.x;
    float s = rowscale ? rowscale[row] : 1.0f;
    float4 v = ((const float4*)(in + row * D))[t];
    v.x *= s; v.y *= s; v.z *= s; v.w *= s;
    __nv_bfloat16 h0 = __float2bfloat16_rn(v.x);
    __nv_bfloat16 h1 = __float2bfloat16_rn(v.y);
    __nv_bfloat16 h2 = __float2bfloat16_rn(v.z);
    __nv_bfloat16 h3 = __float2bfloat16_rn(v.w);
    __nv_bfloat16 l0 = __float2bfloat16_rn(v.x - __bfloat162float(h0));
    __nv_bfloat16 l1 = __float2bfloat16_rn(v.y - __bfloat162float(h1));
    __nv_bfloat16 l2 = __float2bfloat16_rn(v.z - __bfloat162float(h2));
    __nv_bfloat16 l3 = __float2bfloat16_rn(v.w - __bfloat162float(h3));
    uint2 ph = make_uint2(pk(h0, h1), pk(h2, h3));
    uint2 pl = make_uint2(pk(l0, l1), pk(l2, l3));
    ((uint2*)(hi + row * D))[t] = ph;
    ((uint2*)(lo + row * D))[t] = pl;
}

// ---------------- bf16-split tensor-core GEMM -------------------------------
// H[m0:+128, n0:+128] = Ahl @ Wl^T + Xhl @ Wr^T + bias  (fused K=1024)
// Operands pre-split into (hi, lo) bf16; per k-step products:
//   Ah*Bh + Al*Bh + Ah*Bl  (missing Al*Bl ~ 2^-16 relative)
// 4-stage cp.async pipeline; smem tiles [128 rows][64 bf16] (hi cols 0-31,
// lo cols 32-63), 128B rows, XOR-8 16B-chunk swizzle -> conflict-free ldmatrix.
#define NSTAGE 4
#define A_TILE 16384
#define STAGE_B 32768
#define GEMM_SMEM (NSTAGE * STAGE_B)

__global__ void __launch_bounds__(256, 1) gemm_tc_kernel(
    const __nv_bfloat16* __restrict__ aH, const __nv_bfloat16* __restrict__ aL,
    const __nv_bfloat16* __restrict__ xH, const __nv_bfloat16* __restrict__ xL,
    const __nv_bfloat16* __restrict__ wlH, const __nv_bfloat16* __restrict__ wlL,
    const __nv_bfloat16* __restrict__ wrH, const __nv_bfloat16* __restrict__ wrL,
    const float* __restrict__ bias, float* __restrict__ H)
{
    extern __shared__ __align__(1024) char smem[];
    const uint32_t sb = smem_u32(smem);
    const int tid = threadIdx.x, lane = tid & 31, wid = tid >> 5;
    const int m0 = blockIdx.x * 128, n0 = blockIdx.y * 128;

    // ---- loader mapping: 2 threads per row, 2 hi-chunks (16B) each ----
    const int lr = tid >> 1;                 // 0..127
    const int lc = (tid & 1) * 2;            // chunk base 0 or 2
    const int arow = m0 + lr;
    const uint32_t abytes = (arow < N_NODES) ? 16u : 0u;
    const size_t aoff = (size_t)(arow < N_NODES ? arow : 0) * D;
    const size_t woff = (size_t)(n0 + lr) * D;
    const uint32_t rb = (uint32_t)lr * 128;
    const uint32_t r7 = (uint32_t)(lr & 7);

    auto issue = [&](int ci, int s) {
        const int ph = ci >> 4;
        const int k0 = (ci & 15) * 32;
        const __nv_bfloat16* pAH = (ph ? xH : aH) + aoff + k0;
        const __nv_bfloat16* pAL = (ph ? xL : aL) + aoff + k0;
        const __nv_bfloat16* pBH = (ph ? wrH : wlH) + woff + k0;
        const __nv_bfloat16* pBL = (ph ? wrL : wlL) + woff + k0;
        const uint32_t uA = sb + (uint32_t)s * STAGE_B;
        const uint32_t uB = uA + A_TILE;
#pragma unroll
        for (int j = 0; j < 2; j++) {
            const uint32_t c = (uint32_t)(lc + j);
            cp16(uA + rb + (((c    ) ^ r7) << 4), pAH + c * 8, abytes);
            cp16(uA + rb + (((c + 4) ^ r7) << 4), pAL + c * 8, abytes);
            cp16(uB + rb + (((c    ) ^ r7) << 4), pBH + c * 8, 16u);
            cp16(uB + rb + (((c + 4) ^ r7) << 4), pBL + c * 8, 16u);
        }
    };

    // ---- warp tiling: 4x2 warps, each 32(m) x 64(n) ----
    const int wm0 = (wid & 3) * 32, wn0 = (wid >> 2) * 64;
    const int af_r = lane & 15;              // A frag row-in-tile
    const int af_c = lane >> 4;              // A frag chunk offset 0/1
    const int bf_r = (lane & 7) + ((lane >> 4) & 1) * 8;
    const int bf_c = (lane >> 3) & 1;

    float acc[2][8][4];
#pragma unroll
    for (int mi = 0; mi < 2; mi++)
#pragma unroll
        for (int nt = 0; nt < 8; nt++)
#pragma unroll
            for (int q = 0; q < 4; q++) acc[mi][nt][q] = 0.f;

    auto compute = [&](int s) {
        const uint32_t uA = sb + (uint32_t)s * STAGE_B;
        const uint32_t uB = uA + A_TILE;
#pragma unroll
        for (int ks = 0; ks < 2; ks++) {
            uint32_t ah[2][4], al[2][4], bb[4][4];
#pragma unroll
            for (int mi = 0; mi < 2; mi++) {
                int row = wm0 + mi * 16 + af_r;
                int c = ks * 2 + af_c;
                ldsm4(ah[mi], uA + row * 128 + (((c    ) ^ (row & 7)) << 4));
                ldsm4(al[mi], uA + row * 128 + (((c + 4) ^ (row & 7)) << 4));
            }
#pragma unroll
            for (int np = 0; np < 4; np++) {
                int row = wn0 + np * 16 + bf_r;
                int c = ks * 2 + bf_c;
                ldsm4(bb[np], uB + row * 128 + ((c ^ (row & 7)) << 4));
            }
#pragma unroll
            for (int mi = 0; mi < 2; mi++)
#pragma unroll
                for (int nt = 0; nt < 8; nt++)
                    mma16816(acc[mi][nt], ah[mi], &bb[nt >> 1][(nt & 1) * 2]);
#pragma unroll
            for (int mi = 0; mi < 2; mi++)
#pragma unroll
                for (int nt = 0; nt < 8; nt++)
                    mma16816(acc[mi][nt], al[mi], &bb[nt >> 1][(nt & 1) * 2]);
#pragma unroll
            for (int np = 0; np < 4; np++) {
                int row = wn0 + np * 16 + bf_r;
                int c = ks * 2 + bf_c + 4;
                ldsm4(bb[np], uB + row * 128 + ((c ^ (row & 7)) << 4));
            }
#pragma unroll
            for (int mi = 0; mi < 2; mi++)
#pragma unroll
                for (int nt = 0; nt < 8; nt++)
                    mma16816(acc[mi][nt], ah[mi], &bb[nt >> 1][(nt & 1) * 2]);
        }
    };

    // ---- pipeline: 32 chunks of k32 (16 per phase) ----
    for (int s = 0; s < NSTAGE - 1; s++) { issue(s, s); CP_COMMIT(); }
    for (int ci = 0; ci < 32; ci++) {
        CP_WAIT2();
        __syncthreads();
        compute(ci & 3);
        if (ci + NSTAGE - 1 < 32) issue(ci + NSTAGE - 1, (ci + NSTAGE - 1) & 3);
        CP_COMMIT();
    }

    // ---- epilogue: + bias, store fp32 ----
    const int er = lane >> 2, ec = (lane & 3) * 2;
    float bv[8][2];
#pragma unroll
    for (int nt = 0; nt < 8; nt++) {
        bv[nt][0] = __ldg(bias + n0 + wn0 + nt * 8 + ec);
        bv[nt][1] = __ldg(bias + n0 + wn0 + nt * 8 + ec + 1);
    }
#pragma unroll
    for (int mi = 0; mi < 2; mi++) {
        int r0 = m0 + wm0 + mi * 16 + er;
        if (r0 < N_NODES) {
            float* h0 = H + (size_t)r0 * D + n0 + wn0 + ec;
#pragma unroll
            for (int nt = 0; nt < 8; nt++) {
                float2 o = make_float2(acc[mi][nt][0] + bv[nt][0],
                                       acc[mi][nt][1] + bv[nt][1]);
                *(float2*)(h0 + nt * 8) = o;
            }
        }
        int r1 = r0 + 8;
        if (r1 < N_NODES) {
            float* h1 = H + (size_t)r1 * D + n0 + wn0 + ec;
#pragma unroll
            for (int nt = 0; nt < 8; nt++) {
                float2 o = make_float2(acc[mi][nt][2] + bv[nt][0],
                                       acc[mi][nt][3] + bv[nt][1]);
                *(float2*)(h1 + nt * 8) = o;
            }
        }
    }
}

// ---------------- LayerNorm + ReLU + residual (+ fused bf16 split) ----------
__global__ void __launch_bounds__(128) ln_kernel(
    const float* __restrict__ H, const float* __restrict__ Xin,
    const float* __restrict__ gg, const float* __restrict__ bb,
    float* __restrict__ Xout,
    __nv_bfloat16* __restrict__ hi, __nv_bfloat16* __restrict__ lo)
{
    int row = blockIdx.x;
    int t = threadIdx.x;
    int lane = t & 31, wid = t >> 5;

    float4 v = ((const float4*)(H + (size_t)row * D))[t];
    float s  = v.x + v.y + v.z + v.w;
    float sq = v.x * v.x + v.y * v.y + v.z * v.z + v.w * v.w;

#pragma unroll
    for (int off = 16; off > 0; off >>= 1) {
        s  += __shfl_xor_sync(0xFFFFFFFFu, s,  off);
        sq += __shfl_xor_sync(0xFFFFFFFFu, sq, off);
    }
    __shared__ float ss[4], sqs[4];
    if (lane == 0) { ss[wid] = s; sqs[wid] = sq; }
    __syncthreads();
    s  = ss[0]  + ss[1]  + ss[2]  + ss[3];
    sq = sqs[0] + sqs[1] + sqs[2] + sqs[3];

    float mean = s * (1.0f / D);
    float var  = sq * (1.0f / D) - mean * mean;
    float rr   = rsqrtf(var + LN_EPS);

    float4 g4 = ((const float4*)gg)[t];
    float4 b4 = ((const float4*)bb)[t];
    float4 xi = ((const float4*)(Xin + (size_t)row * D))[t];

    float4 o;
    o.x = fmaxf((v.x - mean) * rr * g4.x + b4.x, 0.f) + xi.x;
    o.y = fmaxf((v.y - mean) * rr * g4.y + b4.y, 0.f) + xi.y;
    o.z = fmaxf((v.z - mean) * rr * g4.z + b4.z, 0.f) + xi.z;
    o.w = fmaxf((v.w - mean) * rr * g4.w + b4.w, 0.f) + xi.w;
    ((float4*)(Xout + (size_t)row * D))[t] = o;

    __nv_bfloat16 h0 = __float2bfloat16_rn(o.x);
    __nv_bfloat16 h1 = __float2bfloat16_rn(o.y);
    __nv_bfloat16 h2 = __float2bfloat16_rn(o.z);
    __nv_bfloat16 h3 = __float2bfloat16_rn(o.w);
    __nv_bfloat16 l0 = __float2bfloat16_rn(o.x - __bfloat162float(h0));
    __nv_bfloat16 l1 = __float2bfloat16_rn(o.y - __bfloat162float(h1));
    __nv_bfloat16 l2 = __float2bfloat16_rn(o.z - __bfloat162float(h2));
    __nv_bfloat16 l3 = __float2bfloat16_rn(o.w - __bfloat162float(h3));
    ((uint2*)(hi + (size_t)row * D))[t] = make_uint2(pk(h0, h1), pk(h2, h3));
    ((uint2*)(lo + (size_t)row * D))[t] = make_uint2(pk(l0, l1), pk(l2, l3));
}

// ---------------- launch ----------------------------------------------------
extern "C" void kernel_launch(void* const* d_in, const int* in_sizes, int n_in,
                              void* d_out, int out_size)
{
    const float* x   = (const float*)d_in[0];
    const int*   ei  = (const int*)  d_in[1];
    const float* Wl  = (const float*)d_in[2];
    const float* Wr  = (const float*)d_in[3];
    const float* b   = (const float*)d_in[4];
    const float* lng = (const float*)d_in[5];
    const float* lnb = (const float*)d_in[6];
    float* out = (float*)d_out;

    float *agg, *h, *x0, *x1, *cnt, *inv;
    __nv_bfloat16 *aH, *aL, *xH, *xL, *wlH, *wlL, *wrH, *wrL;
    cudaGetSymbolAddress((void**)&agg, g_agg);
    cudaGetSymbolAddress((void**)&h,   g_h);
    cudaGetSymbolAddress((void**)&x0,  g_x0);
    cudaGetSymbolAddress((void**)&x1,  g_x1);
    cudaGetSymbolAddress((void**)&cnt, g_cnt);
    cudaGetSymbolAddress((void**)&inv, g_inv);
    cudaGetSymbolAddress((void**)&aH,  g_aH);
    cudaGetSymbolAddress((void**)&aL,  g_aL);
    cudaGetSymbolAddress((void**)&xH,  g_xH);
    cudaGetSymbolAddress((void**)&xL,  g_xL);
    cudaGetSymbolAddress((void**)&wlH, g_wlH);
    cudaGetSymbolAddress((void**)&wlL, g_wlL);
    cudaGetSymbolAddress((void**)&wrH, g_wrH);
    cudaGetSymbolAddress((void**)&wrL, g_wrL);

    cudaFuncSetAttribute(gemm_tc_kernel,
                         cudaFuncAttributeMaxDynamicSharedMemorySize, GEMM_SMEM);

    const size_t nd = (size_t)N_NODES * D;

    zero_kernel<<<(N_NODES / 4 + 255) / 256, 256>>>((float4*)cnt, N_NODES / 4);
    count_kernel<<<(N_EDGES + 255) / 256, 256>>>(ei, cnt);
    inv_kernel<<<(N_NODES + 255) / 256, 256>>>(cnt, inv);

    // layer-0 x split
    split_kernel<<<N_NODES, 128>>>(x, nullptr, xH, xL);

    const float* xin = x;
    float* outs[L_LAYERS] = { x0, x1, out };

    dim3 ggrid((N_NODES + 127) / 128, D / 128);   // (782, 4)

    for (int l = 0; l < L_LAYERS; l++) {
        zero_kernel<<<4096, 256>>>((float4*)agg, nd / 4);
        scatter_kernel<<<N_EDGES, 128>>>(xin, ei, agg);
        split_kernel<<<N_NODES, 128>>>(agg, inv, aH, aL);
        split_kernel<<<D, 128>>>(Wl + (size_t)l * D * D, nullptr, wlH, wlL);
        split_kernel<<<D, 128>>>(Wr + (size_t)l * D * D, nullptr, wrH, wrL);
        gemm_tc_kernel<<<ggrid, 256, GEMM_SMEM>>>(aH, aL, xH, xL,
                                                  wlH, wlL, wrH, wrL,
                                                  b + (size_t)l * D, h);
        ln_kernel<<<N_NODES, 128>>>(h, xin, lng + (size_t)l * D,
                                    lnb + (size_t)l * D, outs[l], xH, xL);
        xin = outs[l];
    }
}

// round 4
// speedup vs baseline: 3.0847x; 1.8242x over previous
#include <cuda_runtime.h>
#include <cuda_bf16.h>
#include <cstdint>
#include <math.h>

#define N_NODES 100000
#define N_EDGES 819200
#define D 512
#define L_LAYERS 3
#define LN_EPS 1e-5f
#define SCAN_BS 512
#define SCAN_NBLK ((N_NODES + SCAN_BS - 1) / SCAN_BS)   // 196

// ---------------- scratch (static device globals; no allocation) ------------
__device__ float g_h  [(size_t)N_NODES * D];
__device__ float g_x0 [(size_t)N_NODES * D];
__device__ float g_x1 [(size_t)N_NODES * D];
__device__ float g_inv[N_NODES];
__device__ int   g_deg[N_NODES];
__device__ int   g_rp [N_NODES];
__device__ int   g_cur[N_NODES];
__device__ int   g_bsum[256];
__device__ int   g_adj[N_EDGES];
__device__ __align__(16) __nv_bfloat16 g_aH[(size_t)N_NODES * D];
__device__ __align__(16) __nv_bfloat16 g_aL[(size_t)N_NODES * D];
__device__ __align__(16) __nv_bfloat16 g_xH[(size_t)N_NODES * D];
__device__ __align__(16) __nv_bfloat16 g_xL[(size_t)N_NODES * D];
__device__ __align__(16) __nv_bfloat16 g_wlH[L_LAYERS * D * D];
__device__ __align__(16) __nv_bfloat16 g_wlL[L_LAYERS * D * D];
__device__ __align__(16) __nv_bfloat16 g_wrH[L_LAYERS * D * D];
__device__ __align__(16) __nv_bfloat16 g_wrL[L_LAYERS * D * D];

// ---------------- helpers ---------------------------------------------------
__device__ __forceinline__ uint32_t smem_u32(const void* p) {
    uint32_t a;
    asm("{ .reg .u64 t; cvta.to.shared.u64 t, %1; cvt.u32.u64 %0, t; }"
        : "=r"(a) : "l"(p));
    return a;
}
__device__ __forceinline__ uint32_t pk(__nv_bfloat16 a, __nv_bfloat16 b) {
    uint16_t ua = *(uint16_t*)&a, ub = *(uint16_t*)&b;
    return (uint32_t)ua | ((uint32_t)ub << 16);
}
__device__ __forceinline__ void ldsm4(uint32_t* r, uint32_t addr) {
    asm volatile("ldmatrix.sync.aligned.m8n8.x4.shared.b16 {%0,%1,%2,%3}, [%4];"
                 : "=r"(r[0]), "=r"(r[1]), "=r"(r[2]), "=r"(r[3]) : "r"(addr));
}
__device__ __forceinline__ void mma16816(float* c, const uint32_t* a, const uint32_t* b) {
    asm volatile("mma.sync.aligned.m16n8k16.row.col.f32.bf16.bf16.f32 "
                 "{%0,%1,%2,%3}, {%4,%5,%6,%7}, {%8,%9}, {%0,%1,%2,%3};"
                 : "+f"(c[0]), "+f"(c[1]), "+f"(c[2]), "+f"(c[3])
                 : "r"(a[0]), "r"(a[1]), "r"(a[2]), "r"(a[3]), "r"(b[0]), "r"(b[1]));
}
__device__ __forceinline__ void cp16(uint32_t dst, const void* src, uint32_t bytes) {
    asm volatile("cp.async.cg.shared.global [%0], [%1], 16, %2;"
                 :: "r"(dst), "l"(src), "r"(bytes) : "memory");
}
#define CP_COMMIT() asm volatile("cp.async.commit_group;" ::: "memory")
#define CP_WAIT2()  asm volatile("cp.async.wait_group 2;" ::: "memory")

__device__ __forceinline__ void split2(float v, __nv_bfloat16& h, __nv_bfloat16& l) {
    h = __float2bfloat16_rn(v);
    l = __float2bfloat16_rn(v - __bfloat162float(h));
}

// ---------------- CSR build -------------------------------------------------
__global__ void zero_deg_kernel(int* __restrict__ deg) {
    int i = blockIdx.x * blockDim.x + threadIdx.x;
    if (i < N_NODES) deg[i] = 0;
}
__global__ void count_kernel(const int* __restrict__ ei, int* __restrict__ deg) {
    int e = blockIdx.x * blockDim.x + threadIdx.x;
    if (e < N_EDGES) atomicAdd(&deg[ei[N_EDGES + e]], 1);
}
__global__ void __launch_bounds__(SCAN_BS) scan1_kernel(
    const int* __restrict__ deg, int* __restrict__ rp, int* __restrict__ bsum)
{
    __shared__ int sh[SCAN_BS];
    int t = threadIdx.x;
    int i = blockIdx.x * SCAN_BS + t;
    int v = (i < N_NODES) ? deg[i] : 0;
    sh[t] = v; __syncthreads();
    for (int off = 1; off < SCAN_BS; off <<= 1) {
        int u = (t >= off) ? sh[t - off] : 0;
        __syncthreads();
        sh[t] += u;
        __syncthreads();
    }
    if (i < N_NODES) rp[i] = sh[t] - v;           // exclusive within block
    if (t == SCAN_BS - 1) bsum[blockIdx.x] = sh[t];
}
__global__ void __launch_bounds__(256) scan2_kernel(int* __restrict__ bsum) {
    __shared__ int sh[256];
    int t = threadIdx.x;
    int v = (t < SCAN_NBLK) ? bsum[t] : 0;
    sh[t] = v; __syncthreads();
    for (int off = 1; off < 256; off <<= 1) {
        int u = (t >= off) ? sh[t - off] : 0;
        __syncthreads();
        sh[t] += u;
        __syncthreads();
    }
    if (t < SCAN_NBLK) bsum[t] = sh[t] - v;       // exclusive
}
__global__ void scan3_kernel(const int* __restrict__ deg, int* __restrict__ rp,
                             int* __restrict__ cur, float* __restrict__ inv,
                             const int* __restrict__ bsum)
{
    int i = blockIdx.x * blockDim.x + threadIdx.x;
    if (i < N_NODES) {
        int r = rp[i] + bsum[i >> 9];
        rp[i] = r;
        cur[i] = r;
        inv[i] = 1.0f / (float)max(deg[i], 1);
    }
}
__global__ void fill_kernel(const int* __restrict__ ei, int* __restrict__ cur,
                            int* __restrict__ adj)
{
    int e = blockIdx.x * blockDim.x + threadIdx.x;
    if (e < N_EDGES) {
        int slot = atomicAdd(&cur[ei[N_EDGES + e]], 1);
        adj[slot] = ei[e];
    }
}

// ---------------- CSR gather aggregation + mean + bf16 split ----------------
// one warp per node; lane owns 4 float4 (16 floats) of the 512-wide row
__global__ void __launch_bounds__(256) agg_kernel(
    const float* __restrict__ x, const int* __restrict__ rp,
    const int* __restrict__ deg, const float* __restrict__ inv,
    const int* __restrict__ adj,
    __nv_bfloat16* __restrict__ hi, __nv_bfloat16* __restrict__ lo)
{
    int node = blockIdx.x * 8 + (threadIdx.x >> 5);
    if (node >= N_NODES) return;
    int lane = threadIdx.x & 31;

    float4 acc[4];
#pragma unroll
    for (int q = 0; q < 4; q++) acc[q] = make_float4(0.f, 0.f, 0.f, 0.f);

    int beg = __ldg(&rp[node]);
    int d   = __ldg(&deg[node]);
    for (int j = 0; j < d; j++) {
        int src = __ldg(&adj[beg + j]);
        const float4* row = (const float4*)(x + (size_t)src * D);
#pragma unroll
        for (int q = 0; q < 4; q++) {
            float4 v = __ldg(row + lane + q * 32);
            acc[q].x += v.x; acc[q].y += v.y; acc[q].z += v.z; acc[q].w += v.w;
        }
    }
    float s = __ldg(&inv[node]);
    uint2* ph = (uint2*)(hi + (size_t)node * D);
    uint2* pl = (uint2*)(lo + (size_t)node * D);
#pragma unroll
    for (int q = 0; q < 4; q++) {
        float4 v = acc[q];
        v.x *= s; v.y *= s; v.z *= s; v.w *= s;
        __nv_bfloat16 h0, h1, h2, h3, l0, l1, l2, l3;
        split2(v.x, h0, l0); split2(v.y, h1, l1);
        split2(v.z, h2, l2); split2(v.w, h3, l3);
        ph[lane + q * 32] = make_uint2(pk(h0, h1), pk(h2, h3));
        pl[lane + q * 32] = make_uint2(pk(l0, l1), pk(l2, l3));
    }
}

// ---------------- fp32 -> (bf16 hi, bf16 lo) split --------------------------
__global__ void __launch_bounds__(128) split_kernel(
    const float* __restrict__ in,
    __nv_bfloat16* __restrict__ hi, __nv_bfloat16* __restrict__ lo)
{
    size_t row = blockIdx.x;
    int t = threadIdx.x;
    float4 v = ((const float4*)(in + row * D))[t];
    __nv_bfloat16 h0, h1, h2, h3, l0, l1, l2, l3;
    split2(v.x, h0, l0); split2(v.y, h1, l1);
    split2(v.z, h2, l2); split2(v.w, h3, l3);
    ((uint2*)(hi + row * D))[t] = make_uint2(pk(h0, h1), pk(h2, h3));
    ((uint2*)(lo + row * D))[t] = make_uint2(pk(l0, l1), pk(l2, l3));
}

// ---------------- bf16-split tensor-core GEMM (unchanged, known-good) -------
#define NSTAGE 4
#define A_TILE 16384
#define STAGE_B 32768
#define GEMM_SMEM (NSTAGE * STAGE_B)

__global__ void __launch_bounds__(256, 1) gemm_tc_kernel(
    const __nv_bfloat16* __restrict__ aH, const __nv_bfloat16* __restrict__ aL,
    const __nv_bfloat16* __restrict__ xH, const __nv_bfloat16* __restrict__ xL,
    const __nv_bfloat16* __restrict__ wlH, const __nv_bfloat16* __restrict__ wlL,
    const __nv_bfloat16* __restrict__ wrH, const __nv_bfloat16* __restrict__ wrL,
    const float* __restrict__ bias, float* __restrict__ H)
{
    extern __shared__ __align__(1024) char smem[];
    const uint32_t sb = smem_u32(smem);
    const int tid = threadIdx.x, lane = tid & 31, wid = tid >> 5;
    const int m0 = blockIdx.x * 128, n0 = blockIdx.y * 128;

    const int lr = tid >> 1;
    const int lc = (tid & 1) * 2;
    const int arow = m0 + lr;
    const uint32_t abytes = (arow < N_NODES) ? 16u : 0u;
    const size_t aoff = (size_t)(arow < N_NODES ? arow : 0) * D;
    const size_t woff = (size_t)(n0 + lr) * D;
    const uint32_t rb = (uint32_t)lr * 128;
    const uint32_t r7 = (uint32_t)(lr & 7);

    auto issue = [&](int ci, int s) {
        const int ph = ci >> 4;
        const int k0 = (ci & 15) * 32;
        const __nv_bfloat16* pAH = (ph ? xH : aH) + aoff + k0;
        const __nv_bfloat16* pAL = (ph ? xL : aL) + aoff + k0;
        const __nv_bfloat16* pBH = (ph ? wrH : wlH) + woff + k0;
        const __nv_bfloat16* pBL = (ph ? wrL : wlL) + woff + k0;
        const uint32_t uA = sb + (uint32_t)s * STAGE_B;
        const uint32_t uB = uA + A_TILE;
#pragma unroll
        for (int j = 0; j < 2; j++) {
            const uint32_t c = (uint32_t)(lc + j);
            cp16(uA + rb + (((c    ) ^ r7) << 4), pAH + c * 8, abytes);
            cp16(uA + rb + (((c + 4) ^ r7) << 4), pAL + c * 8, abytes);
            cp16(uB + rb + (((c    ) ^ r7) << 4), pBH + c * 8, 16u);
            cp16(uB + rb + (((c + 4) ^ r7) << 4), pBL + c * 8, 16u);
        }
    };

    const int wm0 = (wid & 3) * 32, wn0 = (wid >> 2) * 64;
    const int af_r = lane & 15;
    const int af_c = lane >> 4;
    const int bf_r = (lane & 7) + ((lane >> 4) & 1) * 8;
    const int bf_c = (lane >> 3) & 1;

    float acc[2][8][4];
#pragma unroll
    for (int mi = 0; mi < 2; mi++)
#pragma unroll
        for (int nt = 0; nt < 8; nt++)
#pragma unroll
            for (int q = 0; q < 4; q++) acc[mi][nt][q] = 0.f;

    auto compute = [&](int s) {
        const uint32_t uA = sb + (uint32_t)s * STAGE_B;
        const uint32_t uB = uA + A_TILE;
#pragma unroll
        for (int ks = 0; ks < 2; ks++) {
            uint32_t ah[2][4], al[2][4], bb[4][4];
#pragma unroll
            for (int mi = 0; mi < 2; mi++) {
                int row = wm0 + mi * 16 + af_r;
                int c = ks * 2 + af_c;
                ldsm4(ah[mi], uA + row * 128 + (((c    ) ^ (row & 7)) << 4));
                ldsm4(al[mi], uA + row * 128 + (((c + 4) ^ (row & 7)) << 4));
            }
#pragma unroll
            for (int np = 0; np < 4; np++) {
                int row = wn0 + np * 16 + bf_r;
                int c = ks * 2 + bf_c;
                ldsm4(bb[np], uB + row * 128 + ((c ^ (row & 7)) << 4));
            }
#pragma unroll
            for (int mi = 0; mi < 2; mi++)
#pragma unroll
                for (int nt = 0; nt < 8; nt++)
                    mma16816(acc[mi][nt], ah[mi], &bb[nt >> 1][(nt & 1) * 2]);
#pragma unroll
            for (int mi = 0; mi < 2; mi++)
#pragma unroll
                for (int nt = 0; nt < 8; nt++)
                    mma16816(acc[mi][nt], al[mi], &bb[nt >> 1][(nt & 1) * 2]);
#pragma unroll
            for (int np = 0; np < 4; np++) {
                int row = wn0 + np * 16 + bf_r;
                int c = ks * 2 + bf_c + 4;
                ldsm4(bb[np], uB + row * 128 + ((c ^ (row & 7)) << 4));
            }
#pragma unroll
            for (int mi = 0; mi < 2; mi++)
#pragma unroll
                for (int nt = 0; nt < 8; nt++)
                    mma16816(acc[mi][nt], ah[mi], &bb[nt >> 1][(nt & 1) * 2]);
        }
    };

    for (int s = 0; s < NSTAGE - 1; s++) { issue(s, s); CP_COMMIT(); }
    for (int ci = 0; ci < 32; ci++) {
        CP_WAIT2();
        __syncthreads();
        compute(ci & 3);
        if (ci + NSTAGE - 1 < 32) issue(ci + NSTAGE - 1, (ci + NSTAGE - 1) & 3);
        CP_COMMIT();
    }

    const int er = lane >> 2, ec = (lane & 3) * 2;
    float bv[8][2];
#pragma unroll
    for (int nt = 0; nt < 8; nt++) {
        bv[nt][0] = __ldg(bias + n0 + wn0 + nt * 8 + ec);
        bv[nt][1] = __ldg(bias + n0 + wn0 + nt * 8 + ec + 1);
    }
#pragma unroll
    for (int mi = 0; mi < 2; mi++) {
        int r0 = m0 + wm0 + mi * 16 + er;
        if (r0 < N_NODES) {
            float* h0 = H + (size_t)r0 * D + n0 + wn0 + ec;
#pragma unroll
            for (int nt = 0; nt < 8; nt++) {
                float2 o = make_float2(acc[mi][nt][0] + bv[nt][0],
                                       acc[mi][nt][1] + bv[nt][1]);
                *(float2*)(h0 + nt * 8) = o;
            }
        }
        int r1 = r0 + 8;
        if (r1 < N_NODES) {
            float* h1 = H + (size_t)r1 * D + n0 + wn0 + ec;
#pragma unroll
            for (int nt = 0; nt < 8; nt++) {
                float2 o = make_float2(acc[mi][nt][2] + bv[nt][0],
                                       acc[mi][nt][3] + bv[nt][1]);
                *(float2*)(h1 + nt * 8) = o;
            }
        }
    }
}

// ---------------- LayerNorm + ReLU + residual (+ fused bf16 split) ----------
__global__ void __launch_bounds__(128) ln_kernel(
    const float* __restrict__ H, const float* __restrict__ Xin,
    const float* __restrict__ gg, const float* __restrict__ bb,
    float* __restrict__ Xout,
    __nv_bfloat16* __restrict__ hi, __nv_bfloat16* __restrict__ lo)
{
    int row = blockIdx.x;
    int t = threadIdx.x;
    int lane = t & 31, wid = t >> 5;

    float4 v = ((const float4*)(H + (size_t)row * D))[t];
    float s  = v.x + v.y + v.z + v.w;
    float sq = v.x * v.x + v.y * v.y + v.z * v.z + v.w * v.w;

#pragma unroll
    for (int off = 16; off > 0; off >>= 1) {
        s  += __shfl_xor_sync(0xFFFFFFFFu, s,  off);
        sq += __shfl_xor_sync(0xFFFFFFFFu, sq, off);
    }
    __shared__ float ss[4], sqs[4];
    if (lane == 0) { ss[wid] = s; sqs[wid] = sq; }
    __syncthreads();
    s  = ss[0]  + ss[1]  + ss[2]  + ss[3];
    sq = sqs[0] + sqs[1] + sqs[2] + sqs[3];

    float mean = s * (1.0f / D);
    float var  = sq * (1.0f / D) - mean * mean;
    float rr   = rsqrtf(var + LN_EPS);

    float4 g4 = ((const float4*)gg)[t];
    float4 b4 = ((const float4*)bb)[t];
    float4 xi = ((const float4*)(Xin + (size_t)row * D))[t];

    float4 o;
    o.x = fmaxf((v.x - mean) * rr * g4.x + b4.x, 0.f) + xi.x;
    o.y = fmaxf((v.y - mean) * rr * g4.y + b4.y, 0.f) + xi.y;
    o.z = fmaxf((v.z - mean) * rr * g4.z + b4.z, 0.f) + xi.z;
    o.w = fmaxf((v.w - mean) * rr * g4.w + b4.w, 0.f) + xi.w;
    ((float4*)(Xout + (size_t)row * D))[t] = o;

    __nv_bfloat16 h0, h1, h2, h3, l0, l1, l2, l3;
    split2(o.x, h0, l0); split2(o.y, h1, l1);
    split2(o.z, h2, l2); split2(o.w, h3, l3);
    ((uint2*)(hi + (size_t)row * D))[t] = make_uint2(pk(h0, h1), pk(h2, h3));
    ((uint2*)(lo + (size_t)row * D))[t] = make_uint2(pk(l0, l1), pk(l2, l3));
}

// ---------------- launch ----------------------------------------------------
extern "C" void kernel_launch(void* const* d_in, const int* in_sizes, int n_in,
                              void* d_out, int out_size)
{
    const float* x   = (const float*)d_in[0];
    const int*   ei  = (const int*)  d_in[1];
    const float* Wl  = (const float*)d_in[2];
    const float* Wr  = (const float*)d_in[3];
    const float* b   = (const float*)d_in[4];
    const float* lng = (const float*)d_in[5];
    const float* lnb = (const float*)d_in[6];
    float* out = (float*)d_out;

    float *h, *x0, *x1, *inv;
    int *deg, *rp, *cur, *bsum, *adj;
    __nv_bfloat16 *aH, *aL, *xH, *xL, *wlH, *wlL, *wrH, *wrL;
    cudaGetSymbolAddress((void**)&h,    g_h);
    cudaGetSymbolAddress((void**)&x0,   g_x0);
    cudaGetSymbolAddress((void**)&x1,   g_x1);
    cudaGetSymbolAddress((void**)&inv,  g_inv);
    cudaGetSymbolAddress((void**)&deg,  g_deg);
    cudaGetSymbolAddress((void**)&rp,   g_rp);
    cudaGetSymbolAddress((void**)&cur,  g_cur);
    cudaGetSymbolAddress((void**)&bsum, g_bsum);
    cudaGetSymbolAddress((void**)&adj,  g_adj);
    cudaGetSymbolAddress((void**)&aH,   g_aH);
    cudaGetSymbolAddress((void**)&aL,   g_aL);
    cudaGetSymbolAddress((void**)&xH,   g_xH);
    cudaGetSymbolAddress((void**)&xL,   g_xL);
    cudaGetSymbolAddress((void**)&wlH,  g_wlH);
    cudaGetSymbolAddress((void**)&wlL,  g_wlL);
    cudaGetSymbolAddress((void**)&wrH,  g_wrH);
    cudaGetSymbolAddress((void**)&wrL,  g_wrL);

    cudaFuncSetAttribute(gemm_tc_kernel,
                         cudaFuncAttributeMaxDynamicSharedMemorySize, GEMM_SMEM);

    // ---- CSR build (once per call; reused by all 3 layers) ----
    zero_deg_kernel<<<(N_NODES + 255) / 256, 256>>>(deg);
    count_kernel<<<(N_EDGES + 255) / 256, 256>>>(ei, deg);
    scan1_kernel<<<SCAN_NBLK, SCAN_BS>>>(deg, rp, bsum);
    scan2_kernel<<<1, 256>>>(bsum);
    scan3_kernel<<<(N_NODES + 255) / 256, 256>>>(deg, rp, cur, inv, bsum);
    fill_kernel<<<(N_EDGES + 255) / 256, 256>>>(ei, cur, adj);

    // ---- pre-split: layer-0 x and all weights ----
    split_kernel<<<N_NODES, 128>>>(x, xH, xL);
    split_kernel<<<L_LAYERS * D, 128>>>(Wl, wlH, wlL);
    split_kernel<<<L_LAYERS * D, 128>>>(Wr, wrH, wrL);

    const float* xin = x;
    float* outs[L_LAYERS] = { x0, x1, out };

    dim3 ggrid((N_NODES + 127) / 128, D / 128);   // (782, 4)

    for (int l = 0; l < L_LAYERS; l++) {
        agg_kernel<<<(N_NODES + 7) / 8, 256>>>(xin, rp, deg, inv, adj, aH, aL);
        gemm_tc_kernel<<<ggrid, 256, GEMM_SMEM>>>(aH, aL, xH, xL,
                                                  wlH + (size_t)l * D * D,
                                                  wlL + (size_t)l * D * D,
                                                  wrH + (size_t)l * D * D,
                                                  wrL + (size_t)l * D * D,
                                                  b + (size_t)l * D, h);
        ln_kernel<<<N_NODES, 128>>>(h, xin, lng + (size_t)l * D,
                                    lnb + (size_t)l * D, outs[l], xH, xL);
        xin = outs[l];
    }
}

// round 6
// speedup vs baseline: 3.0882x; 1.0012x over previous
#include <cuda_runtime.h>
#include <cuda_bf16.h>
#include <cstdint>
#include <math.h>

#define N_NODES 100000
#define N_EDGES 819200
#define D 512
#define L_LAYERS 3
#define LN_EPS 1e-5f
#define SCAN_BS 512
#define SCAN_NBLK ((N_NODES + SCAN_BS - 1) / SCAN_BS)   // 196

// ---------------- scratch (static device globals; no allocation) ------------
__device__ float g_h  [(size_t)N_NODES * D];
__device__ float g_x0 [(size_t)N_NODES * D];
__device__ float g_x1 [(size_t)N_NODES * D];
__device__ float g_inv[N_NODES];
__device__ int   g_deg[N_NODES];
__device__ int   g_rp [N_NODES];
__device__ int   g_cur[N_NODES];
__device__ int   g_bsum[256];
__device__ int   g_adj[N_EDGES];
__device__ __align__(16) __nv_bfloat16 g_aH[(size_t)N_NODES * D];
__device__ __align__(16) __nv_bfloat16 g_aL[(size_t)N_NODES * D];
__device__ __align__(16) __nv_bfloat16 g_xH[(size_t)N_NODES * D];
__device__ __align__(16) __nv_bfloat16 g_xL[(size_t)N_NODES * D];
__device__ __align__(16) __nv_bfloat16 g_wlH[L_LAYERS * D * D];
__device__ __align__(16) __nv_bfloat16 g_wlL[L_LAYERS * D * D];
__device__ __align__(16) __nv_bfloat16 g_wrH[L_LAYERS * D * D];
__device__ __align__(16) __nv_bfloat16 g_wrL[L_LAYERS * D * D];

// ---------------- helpers ---------------------------------------------------
__device__ __forceinline__ uint32_t smem_u32(const void* p) {
    uint32_t a;
    asm("{ .reg .u64 t; cvta.to.shared.u64 t, %1; cvt.u32.u64 %0, t; }"
        : "=r"(a) : "l"(p));
    return a;
}
__device__ __forceinline__ uint32_t pk(__nv_bfloat16 a, __nv_bfloat16 b) {
    uint16_t ua = *(uint16_t*)&a, ub = *(uint16_t*)&b;
    return (uint32_t)ua | ((uint32_t)ub << 16);
}
__device__ __forceinline__ void ldsm4(uint32_t* r, uint32_t addr) {
    asm volatile("ldmatrix.sync.aligned.m8n8.x4.shared.b16 {%0,%1,%2,%3}, [%4];"
                 : "=r"(r[0]), "=r"(r[1]), "=r"(r[2]), "=r"(r[3]) : "r"(addr));
}
__device__ __forceinline__ void mma16816(float* c, const uint32_t* a, const uint32_t* b) {
    asm volatile("mma.sync.aligned.m16n8k16.row.col.f32.bf16.bf16.f32 "
                 "{%0,%1,%2,%3}, {%4,%5,%6,%7}, {%8,%9}, {%0,%1,%2,%3};"
                 : "+f"(c[0]), "+f"(c[1]), "+f"(c[2]), "+f"(c[3])
                 : "r"(a[0]), "r"(a[1]), "r"(a[2]), "r"(a[3]), "r"(b[0]), "r"(b[1]));
}
__device__ __forceinline__ void cp16(uint32_t dst, const void* src, uint32_t bytes) {
    asm volatile("cp.async.cg.shared.global [%0], [%1], 16, %2;"
                 :: "r"(dst), "l"(src), "r"(bytes) : "memory");
}
#define CP_COMMIT() asm volatile("cp.async.commit_group;" ::: "memory")
#define CP_WAIT2()  asm volatile("cp.async.wait_group 2;" ::: "memory")

__device__ __forceinline__ void split2(float v, __nv_bfloat16& h, __nv_bfloat16& l) {
    h = __float2bfloat16_rn(v);
    l = __float2bfloat16_rn(v - __bfloat162float(h));
}

// ---------------- CSR build -------------------------------------------------
__global__ void zero_deg_kernel(int* __restrict__ deg) {
    int i = blockIdx.x * blockDim.x + threadIdx.x;
    if (i < N_NODES) deg[i] = 0;
}
__global__ void count_kernel(const int* __restrict__ ei, int* __restrict__ deg) {
    int e = blockIdx.x * blockDim.x + threadIdx.x;
    if (e < N_EDGES) atomicAdd(&deg[ei[N_EDGES + e]], 1);
}
__global__ void __launch_bounds__(SCAN_BS) scan1_kernel(
    const int* __restrict__ deg, int* __restrict__ rp, int* __restrict__ bsum)
{
    __shared__ int sh[SCAN_BS];
    int t = threadIdx.x;
    int i = blockIdx.x * SCAN_BS + t;
    int v = (i < N_NODES) ? deg[i] : 0;
    sh[t] = v; __syncthreads();
    for (int off = 1; off < SCAN_BS; off <<= 1) {
        int u = (t >= off) ? sh[t - off] : 0;
        __syncthreads();
        sh[t] += u;
        __syncthreads();
    }
    if (i < N_NODES) rp[i] = sh[t] - v;           // exclusive within block
    if (t == SCAN_BS - 1) bsum[blockIdx.x] = sh[t];
}
__global__ void __launch_bounds__(256) scan2_kernel(int* __restrict__ bsum) {
    __shared__ int sh[256];
    int t = threadIdx.x;
    int v = (t < SCAN_NBLK) ? bsum[t] : 0;
    sh[t] = v; __syncthreads();
    for (int off = 1; off < 256; off <<= 1) {
        int u = (t >= off) ? sh[t - off] : 0;
        __syncthreads();
        sh[t] += u;
        __syncthreads();
    }
    if (t < SCAN_NBLK) bsum[t] = sh[t] - v;       // exclusive
}
__global__ void scan3_kernel(const int* __restrict__ deg, int* __restrict__ rp,
                             int* __restrict__ cur, float* __restrict__ inv,
                             const int* __restrict__ bsum)
{
    int i = blockIdx.x * blockDim.x + threadIdx.x;
    if (i < N_NODES) {
        int r = rp[i] + bsum[i >> 9];
        rp[i] = r;
        cur[i] = r;
        inv[i] = 1.0f / (float)max(deg[i], 1);
    }
}
__global__ void fill_kernel(const int* __restrict__ ei, int* __restrict__ cur,
                            int* __restrict__ adj)
{
    int e = blockIdx.x * blockDim.x + threadIdx.x;
    if (e < N_EDGES) {
        int slot = atomicAdd(&cur[ei[N_EDGES + e]], 1);
        adj[slot] = ei[e];
    }
}

// ---------------- CSR gather aggregation + mean + bf16 split ----------------
// one warp per node; lane owns 4 float4 (16 floats); neighbor loop unrolled x2
__global__ void __launch_bounds__(256) agg_kernel(
    const float* __restrict__ x, const int* __restrict__ rp,
    const int* __restrict__ deg, const float* __restrict__ inv,
    const int* __restrict__ adj,
    __nv_bfloat16* __restrict__ hi, __nv_bfloat16* __restrict__ lo)
{
    int node = blockIdx.x * 8 + (threadIdx.x >> 5);
    if (node >= N_NODES) return;
    int lane = threadIdx.x & 31;

    float4 acc[4];
#pragma unroll
    for (int q = 0; q < 4; q++) acc[q] = make_float4(0.f, 0.f, 0.f, 0.f);

    int beg = __ldg(&rp[node]);
    int d   = __ldg(&deg[node]);
    int j = 0;
    for (; j + 2 <= d; j += 2) {
        int s0 = __ldg(&adj[beg + j]);
        int s1 = __ldg(&adj[beg + j + 1]);
        const float4* r0 = (const float4*)(x + (size_t)s0 * D);
        const float4* r1 = (const float4*)(x + (size_t)s1 * D);
        float4 v0[4], v1[4];
#pragma unroll
        for (int q = 0; q < 4; q++) v0[q] = __ldg(r0 + lane + q * 32);
#pragma unroll
        for (int q = 0; q < 4; q++) v1[q] = __ldg(r1 + lane + q * 32);
#pragma unroll
        for (int q = 0; q < 4; q++) {
            acc[q].x += v0[q].x + v1[q].x;
            acc[q].y += v0[q].y + v1[q].y;
            acc[q].z += v0[q].z + v1[q].z;
            acc[q].w += v0[q].w + v1[q].w;
        }
    }
    if (j < d) {
        int s0 = __ldg(&adj[beg + j]);
        const float4* r0 = (const float4*)(x + (size_t)s0 * D);
#pragma unroll
        for (int q = 0; q < 4; q++) {
            float4 v = __ldg(r0 + lane + q * 32);
            acc[q].x += v.x; acc[q].y += v.y; acc[q].z += v.z; acc[q].w += v.w;
        }
    }
    float s = __ldg(&inv[node]);
    uint2* ph = (uint2*)(hi + (size_t)node * D);
    uint2* pl = (uint2*)(lo + (size_t)node * D);
#pragma unroll
    for (int q = 0; q < 4; q++) {
        float4 v = acc[q];
        v.x *= s; v.y *= s; v.z *= s; v.w *= s;
        __nv_bfloat16 h0, h1, h2, h3, l0, l1, l2, l3;
        split2(v.x, h0, l0); split2(v.y, h1, l1);
        split2(v.z, h2, l2); split2(v.w, h3, l3);
        ph[lane + q * 32] = make_uint2(pk(h0, h1), pk(h2, h3));
        pl[lane + q * 32] = make_uint2(pk(l0, l1), pk(l2, l3));
    }
}

// ---------------- fp32 -> (bf16 hi, bf16 lo) split --------------------------
__global__ void __launch_bounds__(128) split_kernel(
    const float* __restrict__ in,
    __nv_bfloat16* __restrict__ hi, __nv_bfloat16* __restrict__ lo)
{
    size_t row = blockIdx.x;
    int t = threadIdx.x;
    float4 v = ((const float4*)(in + row * D))[t];
    __nv_bfloat16 h0, h1, h2, h3, l0, l1, l2, l3;
    split2(v.x, h0, l0); split2(v.y, h1, l1);
    split2(v.z, h2, l2); split2(v.w, h3, l3);
    ((uint2*)(hi + row * D))[t] = make_uint2(pk(h0, h1), pk(h2, h3));
    ((uint2*)(lo + row * D))[t] = make_uint2(pk(l0, l1), pk(l2, l3));
}

// ---------------- bf16-split tensor-core GEMM -------------------------------
// grid = (D/128, m-blocks): blockIdx.x = N-block (fast) -> 4 blocks sharing
// the same A rows are launch-adjacent => A tile served from L2 (~4x less
// A-operand DRAM traffic than the previous (m, n) rasterization).
#define NSTAGE 4
#define A_TILE 16384
#define STAGE_B 32768
#define GEMM_SMEM (NSTAGE * STAGE_B)

__global__ void __launch_bounds__(256, 1) gemm_tc_kernel(
    const __nv_bfloat16* __restrict__ aH, const __nv_bfloat16* __restrict__ aL,
    const __nv_bfloat16* __restrict__ xH, const __nv_bfloat16* __restrict__ xL,
    const __nv_bfloat16* __restrict__ wlH, const __nv_bfloat16* __restrict__ wlL,
    const __nv_bfloat16* __restrict__ wrH, const __nv_bfloat16* __restrict__ wrL,
    const float* __restrict__ bias, float* __restrict__ H)
{
    extern __shared__ __align__(1024) char smem[];
    const uint32_t sb = smem_u32(smem);
    const int tid = threadIdx.x, lane = tid & 31, wid = tid >> 5;
    const int m0 = blockIdx.y * 128, n0 = blockIdx.x * 128;

    const int lr = tid >> 1;
    const int lc = (tid & 1) * 2;
    const int arow = m0 + lr;
    const uint32_t abytes = (arow < N_NODES) ? 16u : 0u;
    const size_t aoff = (size_t)(arow < N_NODES ? arow : 0) * D;
    const size_t woff = (size_t)(n0 + lr) * D;
    const uint32_t rb = (uint32_t)lr * 128;
    const uint32_t r7 = (uint32_t)(lr & 7);

    auto issue = [&](int ci, int s) {
        const int ph = ci >> 4;
        const int k0 = (ci & 15) * 32;
        const __nv_bfloat16* pAH = (ph ? xH : aH) + aoff + k0;
        const __nv_bfloat16* pAL = (ph ? xL : aL) + aoff + k0;
        const __nv_bfloat16* pBH = (ph ? wrH : wlH) + woff + k0;
        const __nv_bfloat16* pBL = (ph ? wrL : wlL) + woff + k0;
        const uint32_t uA = sb + (uint32_t)s * STAGE_B;
        const uint32_t uB = uA + A_TILE;
#pragma unroll
        for (int j = 0; j < 2; j++) {
            const uint32_t c = (uint32_t)(lc + j);
            cp16(uA + rb + (((c    ) ^ r7) << 4), pAH + c * 8, abytes);
            cp16(uA + rb + (((c + 4) ^ r7) << 4), pAL + c * 8, abytes);
            cp16(uB + rb + (((c    ) ^ r7) << 4), pBH + c * 8, 16u);
            cp16(uB + rb + (((c + 4) ^ r7) << 4), pBL + c * 8, 16u);
        }
    };

    const int wm0 = (wid & 3) * 32, wn0 = (wid >> 2) * 64;
    const int af_r = lane & 15;
    const int af_c = lane >> 4;
    const int bf_r = (lane & 7) + ((lane >> 4) & 1) * 8;
    const int bf_c = (lane >> 3) & 1;

    float acc[2][8][4];
#pragma unroll
    for (int mi = 0; mi < 2; mi++)
#pragma unroll
        for (int nt = 0; nt < 8; nt++)
#pragma unroll
            for (int q = 0; q < 4; q++) acc[mi][nt][q] = 0.f;

    auto compute = [&](int s) {
        const uint32_t uA = sb + (uint32_t)s * STAGE_B;
        const uint32_t uB = uA + A_TILE;
#pragma unroll
        for (int ks = 0; ks < 2; ks++) {
            uint32_t ah[2][4], al[2][4], bb[4][4];
#pragma unroll
            for (int mi = 0; mi < 2; mi++) {
                int row = wm0 + mi * 16 + af_r;
                int c = ks * 2 + af_c;
                ldsm4(ah[mi], uA + row * 128 + (((c    ) ^ (row & 7)) << 4));
                ldsm4(al[mi], uA + row * 128 + (((c + 4) ^ (row & 7)) << 4));
            }
#pragma unroll
            for (int np = 0; np < 4; np++) {
                int row = wn0 + np * 16 + bf_r;
                int c = ks * 2 + bf_c;
                ldsm4(bb[np], uB + row * 128 + ((c ^ (row & 7)) << 4));
            }
#pragma unroll
            for (int mi = 0; mi < 2; mi++)
#pragma unroll
                for (int nt = 0; nt < 8; nt++)
                    mma16816(acc[mi][nt], ah[mi], &bb[nt >> 1][(nt & 1) * 2]);
#pragma unroll
            for (int mi = 0; mi < 2; mi++)
#pragma unroll
                for (int nt = 0; nt < 8; nt++)
                    mma16816(acc[mi][nt], al[mi], &bb[nt >> 1][(nt & 1) * 2]);
#pragma unroll
            for (int np = 0; np < 4; np++) {
                int row = wn0 + np * 16 + bf_r;
                int c = ks * 2 + bf_c + 4;
                ldsm4(bb[np], uB + row * 128 + ((c ^ (row & 7)) << 4));
            }
#pragma unroll
            for (int mi = 0; mi < 2; mi++)
#pragma unroll
                for (int nt = 0; nt < 8; nt++)
                    mma16816(acc[mi][nt], ah[mi], &bb[nt >> 1][(nt & 1) * 2]);
        }
    };

    for (int s = 0; s < NSTAGE - 1; s++) { issue(s, s); CP_COMMIT(); }
    for (int ci = 0; ci < 32; ci++) {
        CP_WAIT2();
        __syncthreads();
        compute(ci & 3);
        if (ci + NSTAGE - 1 < 32) issue(ci + NSTAGE - 1, (ci + NSTAGE - 1) & 3);
        CP_COMMIT();
    }

    const int er = lane >> 2, ec = (lane & 3) * 2;
    float bv[8][2];
#pragma unroll
    for (int nt = 0; nt < 8; nt++) {
        bv[nt][0] = __ldg(bias + n0 + wn0 + nt * 8 + ec);
        bv[nt][1] = __ldg(bias + n0 + wn0 + nt * 8 + ec + 1);
    }
#pragma unroll
    for (int mi = 0; mi < 2; mi++) {
        int r0 = m0 + wm0 + mi * 16 + er;
        if (r0 < N_NODES) {
            float* h0 = H + (size_t)r0 * D + n0 + wn0 + ec;
#pragma unroll
            for (int nt = 0; nt < 8; nt++) {
                float2 o = make_float2(acc[mi][nt][0] + bv[nt][0],
                                       acc[mi][nt][1] + bv[nt][1]);
                *(float2*)(h0 + nt * 8) = o;
            }
        }
        int r1 = r0 + 8;
        if (r1 < N_NODES) {
            float* h1 = H + (size_t)r1 * D + n0 + wn0 + ec;
#pragma unroll
            for (int nt = 0; nt < 8; nt++) {
                float2 o = make_float2(acc[mi][nt][2] + bv[nt][0],
                                       acc[mi][nt][3] + bv[nt][1]);
                *(float2*)(h1 + nt * 8) = o;
            }
        }
    }
}

// ---------------- LayerNorm + ReLU + residual (+ fused bf16 split) ----------
__global__ void __launch_bounds__(128) ln_kernel(
    const float* __restrict__ H, const float* __restrict__ Xin,
    const float* __restrict__ gg, const float* __restrict__ bb,
    float* __restrict__ Xout,
    __nv_bfloat16* __restrict__ hi, __nv_bfloat16* __restrict__ lo)
{
    int row = blockIdx.x;
    int t = threadIdx.x;
    int lane = t & 31, wid = t >> 5;

    float4 v = ((const float4*)(H + (size_t)row * D))[t];
    float s  = v.x + v.y + v.z + v.w;
    float sq = v.x * v.x + v.y * v.y + v.z * v.z + v.w * v.w;

#pragma unroll
    for (int off = 16; off > 0; off >>= 1) {
        s  += __shfl_xor_sync(0xFFFFFFFFu, s,  off);
        sq += __shfl_xor_sync(0xFFFFFFFFu, sq, off);
    }
    __shared__ float ss[4], sqs[4];
    if (lane == 0) { ss[wid] = s; sqs[wid] = sq; }
    __syncthreads();
    s  = ss[0]  + ss[1]  + ss[2]  + ss[3];
    sq = sqs[0] + sqs[1] + sqs[2] + sqs[3];

    float mean = s * (1.0f / D);
    float var  = sq * (1.0f / D) - mean * mean;
    float rr   = rsqrtf(var + LN_EPS);

    float4 g4 = ((const float4*)gg)[t];
    float4 b4 = ((const float4*)bb)[t];
    float4 xi = ((const float4*)(Xin + (size_t)row * D))[t];

    float4 o;
    o.x = fmaxf((v.x - mean) * rr * g4.x + b4.x, 0.f) + xi.x;
    o.y = fmaxf((v.y - mean) * rr * g4.y + b4.y, 0.f) + xi.y;
    o.z = fmaxf((v.z - mean) * rr * g4.z + b4.z, 0.f) + xi.z;
    o.w = fmaxf((v.w - mean) * rr * g4.w + b4.w, 0.f) + xi.w;
    ((float4*)(Xout + (size_t)row * D))[t] = o;

    __nv_bfloat16 h0, h1, h2, h3, l0, l1, l2, l3;
    split2(o.x, h0, l0); split2(o.y, h1, l1);
    split2(o.z, h2, l2); split2(o.w, h3, l3);
    ((uint2*)(hi + (size_t)row * D))[t] = make_uint2(pk(h0, h1), pk(h2, h3));
    ((uint2*)(lo + (size_t)row * D))[t] = make_uint2(pk(l0, l1), pk(l2, l3));
}

// ---------------- launch ----------------------------------------------------
extern "C" void kernel_launch(void* const* d_in, const int* in_sizes, int n_in,
                              void* d_out, int out_size)
{
    const float* x   = (const float*)d_in[0];
    const int*   ei  = (const int*)  d_in[1];
    const float* Wl  = (const float*)d_in[2];
    const float* Wr  = (const float*)d_in[3];
    const float* b   = (const float*)d_in[4];
    const float* lng = (const float*)d_in[5];
    const float* lnb = (const float*)d_in[6];
    float* out = (float*)d_out;

    float *h, *x0, *x1, *inv;
    int *deg, *rp, *cur, *bsum, *adj;
    __nv_bfloat16 *aH, *aL, *xH, *xL, *wlH, *wlL, *wrH, *wrL;
    cudaGetSymbolAddress((void**)&h,    g_h);
    cudaGetSymbolAddress((void**)&x0,   g_x0);
    cudaGetSymbolAddress((void**)&x1,   g_x1);
    cudaGetSymbolAddress((void**)&inv,  g_inv);
    cudaGetSymbolAddress((void**)&deg,  g_deg);
    cudaGetSymbolAddress((void**)&rp,   g_rp);
    cudaGetSymbolAddress((void**)&cur,  g_cur);
    cudaGetSymbolAddress((void**)&bsum, g_bsum);
    cudaGetSymbolAddress((void**)&adj,  g_adj);
    cudaGetSymbolAddress((void**)&aH,   g_aH);
    cudaGetSymbolAddress((void**)&aL,   g_aL);
    cudaGetSymbolAddress((void**)&xH,   g_xH);
    cudaGetSymbolAddress((void**)&xL,   g_xL);
    cudaGetSymbolAddress((void**)&wlH,  g_wlH);
    cudaGetSymbolAddress((void**)&wlL,  g_wlL);
    cudaGetSymbolAddress((void**)&wrH,  g_wrH);
    cudaGetSymbolAddress((void**)&wrL,  g_wrL);

    cudaFuncSetAttribute(gemm_tc_kernel,
                         cudaFuncAttributeMaxDynamicSharedMemorySize, GEMM_SMEM);

    // ---- CSR build (once per call; reused by all 3 layers) ----
    zero_deg_kernel<<<(N_NODES + 255) / 256, 256>>>(deg);
    count_kernel<<<(N_EDGES + 255) / 256, 256>>>(ei, deg);
    scan1_kernel<<<SCAN_NBLK, SCAN_BS>>>(deg, rp, bsum);
    scan2_kernel<<<1, 256>>>(bsum);
    scan3_kernel<<<(N_NODES + 255) / 256, 256>>>(deg, rp, cur, inv, bsum);
    fill_kernel<<<(N_EDGES + 255) / 256, 256>>>(ei, cur, adj);

    // ---- pre-split: layer-0 x and all weights ----
    split_kernel<<<N_NODES, 128>>>(x, xH, xL);
    split_kernel<<<L_LAYERS * D, 128>>>(Wl, wlH, wlL);
    split_kernel<<<L_LAYERS * D, 128>>>(Wr, wrH, wrL);

    const float* xin = x;
    float* outs[L_LAYERS] = { x0, x1, out };

    dim3 ggrid(D / 128, (N_NODES + 127) / 128);   // (4, 782): n fast, m slow

    for (int l = 0; l < L_LAYERS; l++) {
        agg_kernel<<<(N_NODES + 7) / 8, 256>>>(xin, rp, deg, inv, adj, aH, aL);
        gemm_tc_kernel<<<ggrid, 256, GEMM_SMEM>>>(aH, aL, xH, xL,
                                                  wlH + (size_t)l * D * D,
                                                  wlL + (size_t)l * D * D,
                                                  wrH + (size_t)l * D * D,
                                                  wrL + (size_t)l * D * D,
                                                  b + (size_t)l * D, h);
        ln_kernel<<<N_NODES, 128>>>(h, xin, lng + (size_t)l * D,
                                    lnb + (size_t)l * D, outs[l], xH, xL);
        xin = outs[l];
    }
}